// round 4
// baseline (speedup 1.0000x reference)
#include <cuda_runtime.h>

#define T_LEN   4096
#define IN_SZ   128
#define R_SZ    2048
#define NCTA    128
#define ROWS_PER_CTA 16     // 2048 / 128
#define THREADS_SCAN 256
#define INV_SQRT_R 0.022097086912079608f   // 1/sqrt(2048)

// Scratch: batched input projection U[t][r] = input[t] @ W_in^T + bias
__device__ float g_U[(size_t)T_LEN * R_SZ];
__device__ int   g_flags[NCTA];

// packed 2xf32 FMA (PTX ISA 8.6, sm_100+)
__device__ __forceinline__ void fma2(unsigned long long& d,
                                     unsigned long long a,
                                     unsigned long long b) {
    asm("fma.rn.f32x2 %0, %1, %2, %0;" : "+l"(d) : "l"(a), "l"(b));
}
__device__ __forceinline__ float unpack_sum(unsigned long long v) {
    float lo = __uint_as_float((unsigned)(v & 0xffffffffULL));
    float hi = __uint_as_float((unsigned)(v >> 32));
    return lo + hi;
}
// Truly volatile 16B flag load — compiler may NOT hoist this out of the
// spin loop (the R3 deadlock was __ldcg being hoisted as loop-invariant).
__device__ __forceinline__ int4 ld_flags_volatile(const int4* p) {
    int4 v;
    asm volatile("ld.volatile.global.v4.s32 {%0,%1,%2,%3}, [%4];"
                 : "=r"(v.x), "=r"(v.y), "=r"(v.z), "=r"(v.w)
                 : "l"(p) : "memory");
    return v;
}

// ---------------------------------------------------------------------------
__global__ void init_kernel() {
    if (threadIdx.x < NCTA) g_flags[threadIdx.x] = 0;
}

// ---------------------------------------------------------------------------
// Projection GEMM: U = input @ W_in^T + bias.  (4096 x 2048, K=128)
// ---------------------------------------------------------------------------
#define PJ_KT 32
__global__ __launch_bounds__(256) void proj_kernel(
    const float* __restrict__ inp,   // [T_LEN][IN_SZ]
    const float* __restrict__ Win,   // [R_SZ][IN_SZ]
    const float* __restrict__ bias)  // [R_SZ]
{
    __shared__ float sA[PJ_KT][64];  // [k][t]
    __shared__ float sB[PJ_KT][64];  // [k][r]

    const int tid = threadIdx.x;
    const int t0 = blockIdx.y * 64;
    const int r0 = blockIdx.x * 64;
    const int tx = tid & 15;
    const int ty = tid >> 4;

    float acc[4][4];
#pragma unroll
    for (int i = 0; i < 4; i++)
#pragma unroll
        for (int j = 0; j < 4; j++) acc[i][j] = 0.0f;

    for (int kc = 0; kc < IN_SZ; kc += PJ_KT) {
        __syncthreads();
#pragma unroll
        for (int it = 0; it < 2; it++) {
            int i   = tid + 256 * it;
            int row = i >> 3;
            int kq  = i & 7;
            float4 va = *(const float4*)(inp + (size_t)(t0 + row) * IN_SZ + kc + 4 * kq);
            sA[4 * kq + 0][row] = va.x;
            sA[4 * kq + 1][row] = va.y;
            sA[4 * kq + 2][row] = va.z;
            sA[4 * kq + 3][row] = va.w;
            float4 vb = *(const float4*)(Win + (size_t)(r0 + row) * IN_SZ + kc + 4 * kq);
            sB[4 * kq + 0][row] = vb.x;
            sB[4 * kq + 1][row] = vb.y;
            sB[4 * kq + 2][row] = vb.z;
            sB[4 * kq + 3][row] = vb.w;
        }
        __syncthreads();
#pragma unroll
        for (int k = 0; k < PJ_KT; k++) {
            float a[4], b[4];
#pragma unroll
            for (int i = 0; i < 4; i++) a[i] = sA[k][tx + 16 * i];
#pragma unroll
            for (int j = 0; j < 4; j++) b[j] = sB[k][ty + 16 * j];
#pragma unroll
            for (int i = 0; i < 4; i++)
#pragma unroll
                for (int j = 0; j < 4; j++) acc[i][j] += a[i] * b[j];
        }
    }

#pragma unroll
    for (int j = 0; j < 4; j++) {
        const int r = r0 + ty + 16 * j;
        const float bj = bias[r];
#pragma unroll
        for (int i = 0; i < 4; i++) {
            const int t = t0 + tx + 16 * i;
            g_U[(size_t)t * R_SZ + r] = acc[i][j] + bj;
        }
    }
}

// ---------------------------------------------------------------------------
// Persistent ESN scan. 128 CTAs, 16 rows each, weights register-resident,
// f32x2 packed FMAs, distributed flag barrier, split-half shfl reduction.
// ---------------------------------------------------------------------------
__global__ __launch_bounds__(THREADS_SCAN, 1) void scan_kernel(
    const float* __restrict__ Wres,  // [R_SZ][R_SZ]
    float* __restrict__ out)         // [T_LEN][R_SZ]
{
    __shared__ ulonglong2 s_sm2[R_SZ / 4];   // full state, 8 KB (as 2xf32 pairs)
    __shared__ float r_sm[ROWS_PER_CTA];     // this CTA's 16 new values

    const int tid  = threadIdx.x;
    const int warp = tid >> 5;
    const int lane = tid & 31;
    const int bid  = blockIdx.x;
    const int rowA = bid * ROWS_PER_CTA + 2 * warp;

    // Preload weights into registers as packed f32x2.
    // Thread (warp w, lane l): rows {rowA,rowA+1}, cols 4*l + 128*k (+0..3).
    unsigned long long wA2[32], wB2[32];
    {
        const ulonglong2* pA = (const ulonglong2*)(Wres + (size_t)rowA * R_SZ + 4 * lane);
        const ulonglong2* pB = (const ulonglong2*)(Wres + (size_t)(rowA + 1) * R_SZ + 4 * lane);
#pragma unroll
        for (int k = 0; k < 16; k++) {
            ulonglong2 va = pA[32 * k];
            wA2[2 * k] = va.x; wA2[2 * k + 1] = va.y;
            ulonglong2 vb = pB[32 * k];
            wB2[2 * k] = vb.x; wB2[2 * k + 1] = vb.y;
        }
    }

    // lane 0 owns rowA's carry, lane 16 owns rowB's carry
    const bool is_owner = (lane == 0) || (lane == 16);
    const int  my_row   = rowA + (lane >> 4);          // rowA or rowA+1
    float xp = 0.0f;                                   // previous value of my_row

    for (int t = 0; t < T_LEN; t++) {
        // ---- hoisted independent load: input projection for this step ----
        float u = 0.f;
        if (is_owner) u = __ldg(g_U + (size_t)t * R_SZ + my_row);

        // ---- wait for all CTAs to have published step t-1 ----
        if (t > 0 && warp == 0) {
            const int4* fp = (const int4*)g_flags;
            int4 v;
            do {
                v = ld_flags_volatile(fp + lane);
            } while (!__all_sync(0xffffffffu,
                                 v.x >= t && v.y >= t && v.z >= t && v.w >= t));
        }
        __syncthreads();

        // ---- bring state into SMEM ----
        if (t == 0) {
            for (int i = tid; i < R_SZ / 4; i += THREADS_SCAN)
                s_sm2[i] = make_ulonglong2(0ull, 0ull);
        } else {
            const ulonglong2* prev = (const ulonglong2*)(out + (size_t)(t - 1) * R_SZ);
            for (int i = tid; i < R_SZ / 4; i += THREADS_SCAN)
                s_sm2[i] = __ldcg(prev + i);
        }
        __syncthreads();

        // ---- register-resident matvec (packed f32x2) ----
        unsigned long long a0 = 0ull, a1 = 0ull;
#pragma unroll
        for (int k = 0; k < 16; k++) {
            const ulonglong2 s2 = s_sm2[lane + 32 * k];
            fma2(a0, wA2[2 * k],     s2.x);
            fma2(a0, wA2[2 * k + 1], s2.y);
            fma2(a1, wB2[2 * k],     s2.x);
            fma2(a1, wB2[2 * k + 1], s2.y);
        }
        float f0 = unpack_sum(a0);
        float f1 = unpack_sum(a1);

        // ---- split-half reduction: one cross-half level for both rows,
        //      then 4 in-half levels. lane 0 -> row A sum, lane 16 -> row B. ----
        f0 += __shfl_xor_sync(0xffffffffu, f0, 16);
        f1 += __shfl_xor_sync(0xffffffffu, f1, 16);
        float v = (lane < 16) ? f0 : f1;
#pragma unroll
        for (int off = 8; off > 0; off >>= 1)
            v += __shfl_xor_sync(0xffffffffu, v, off);

        if (is_owner) {
            const float x = 0.1f * xp + 0.9f * erff(v + u) * INV_SQRT_R;
            xp = x;
            r_sm[2 * warp + (lane >> 4)] = x;
        }
        __syncthreads();

        // ---- publish: single thread (warp 7) stores 64B + fence + flag,
        //      while warp 0 proceeds to poll for the next step ----
        if (warp == 7 && lane == 0) {
            float4* dst = (float4*)(out + (size_t)t * R_SZ + bid * ROWS_PER_CTA);
            const float4* rs = (const float4*)r_sm;
            float4 v0 = rs[0], v1 = rs[1], v2 = rs[2], v3 = rs[3];
            dst[0] = v0; dst[1] = v1; dst[2] = v2; dst[3] = v3;
            __threadfence();
            *(volatile int*)(g_flags + bid) = t + 1;
        }
    }
}

// ---------------------------------------------------------------------------
extern "C" void kernel_launch(void* const* d_in, const int* in_sizes, int n_in,
                              void* d_out, int out_size)
{
    const float* input = (const float*)d_in[0];  // [4096][128]
    const float* Win   = (const float*)d_in[1];  // [2048][128]
    const float* Wres  = (const float*)d_in[2];  // [2048][2048]
    const float* bias  = (const float*)d_in[3];  // [2048]
    float* out = (float*)d_out;                  // [4096][2048]

    init_kernel<<<1, NCTA>>>();

    dim3 pg(R_SZ / 64, T_LEN / 64);              // (32, 64)
    proj_kernel<<<pg, 256>>>(input, Win, bias);

    scan_kernel<<<NCTA, THREADS_SCAN>>>(Wres, out);
}

// round 5
// speedup vs baseline: 3.1841x; 3.1841x over previous
#include <cuda_runtime.h>

#define T_LEN   4096
#define IN_SZ   128
#define R_SZ    2048
#define NCTA    128
#define ROWS_PER_CTA 16       // 2048 / 128
#define THREADS_SCAN 256
#define CHUNKS_PER_CTA 6      // 16 rows -> 5 chunks x3 + 1 chunk x1
#define NCHUNK (NCTA * CHUNKS_PER_CTA)   // 768 == THREADS_SCAN * 3
#define INV_SQRT_R 0.022097086912079608f // 1/sqrt(2048)

// Scratch: batched input projection U[t][r] = input[t] @ W_in^T + bias
__device__ float g_U[(size_t)T_LEN * R_SZ];
// Self-validating state chunks: {d0,d1,d2, tag_as_float}, double-buffered by
// step parity. A 16B aligned STG.128 is single-copy atomic, so tag==t implies
// the 3 data floats in the same word are from step t. No fences, no flags.
__device__ float4 g_chunks[2][NCHUNK];

__device__ __forceinline__ float4 ld_chunk_volatile(const float4* p) {
    float4 v;
    asm volatile("ld.volatile.global.v4.f32 {%0,%1,%2,%3}, [%4];"
                 : "=f"(v.x), "=f"(v.y), "=f"(v.z), "=f"(v.w)
                 : "l"(p) : "memory");
    return v;
}
__device__ __forceinline__ void st_chunk_volatile(float4* p, float4 v) {
    asm volatile("st.volatile.global.v4.f32 [%0], {%1,%2,%3,%4};"
                 :: "l"(p), "f"(v.x), "f"(v.y), "f"(v.z), "f"(v.w)
                 : "memory");
}

// ---------------------------------------------------------------------------
// Reset all chunk tags (stale tags from a previous graph replay would
// otherwise satisfy this replay's polls with stale data).
// ---------------------------------------------------------------------------
__global__ void init_kernel() {
    int i = blockIdx.x * blockDim.x + threadIdx.x;   // 0 .. 2*NCHUNK-1
    ((float4*)g_chunks)[i] = make_float4(0.f, 0.f, 0.f, 0.f);
}

// ---------------------------------------------------------------------------
// Projection GEMM: U = input @ W_in^T + bias.  (4096 x 2048, K=128)
// ---------------------------------------------------------------------------
#define PJ_KT 32
__global__ __launch_bounds__(256) void proj_kernel(
    const float* __restrict__ inp,   // [T_LEN][IN_SZ]
    const float* __restrict__ Win,   // [R_SZ][IN_SZ]
    const float* __restrict__ bias)  // [R_SZ]
{
    __shared__ float sA[PJ_KT][64];  // [k][t]
    __shared__ float sB[PJ_KT][64];  // [k][r]

    const int tid = threadIdx.x;
    const int t0 = blockIdx.y * 64;
    const int r0 = blockIdx.x * 64;
    const int tx = tid & 15;
    const int ty = tid >> 4;

    float acc[4][4];
#pragma unroll
    for (int i = 0; i < 4; i++)
#pragma unroll
        for (int j = 0; j < 4; j++) acc[i][j] = 0.0f;

    for (int kc = 0; kc < IN_SZ; kc += PJ_KT) {
        __syncthreads();
#pragma unroll
        for (int it = 0; it < 2; it++) {
            int i   = tid + 256 * it;
            int row = i >> 3;
            int kq  = i & 7;
            float4 va = *(const float4*)(inp + (size_t)(t0 + row) * IN_SZ + kc + 4 * kq);
            sA[4 * kq + 0][row] = va.x;
            sA[4 * kq + 1][row] = va.y;
            sA[4 * kq + 2][row] = va.z;
            sA[4 * kq + 3][row] = va.w;
            float4 vb = *(const float4*)(Win + (size_t)(r0 + row) * IN_SZ + kc + 4 * kq);
            sB[4 * kq + 0][row] = vb.x;
            sB[4 * kq + 1][row] = vb.y;
            sB[4 * kq + 2][row] = vb.z;
            sB[4 * kq + 3][row] = vb.w;
        }
        __syncthreads();
#pragma unroll
        for (int k = 0; k < PJ_KT; k++) {
            float a[4], b[4];
#pragma unroll
            for (int i = 0; i < 4; i++) a[i] = sA[k][tx + 16 * i];
#pragma unroll
            for (int j = 0; j < 4; j++) b[j] = sB[k][ty + 16 * j];
#pragma unroll
            for (int i = 0; i < 4; i++)
#pragma unroll
                for (int j = 0; j < 4; j++) acc[i][j] += a[i] * b[j];
        }
    }

#pragma unroll
    for (int j = 0; j < 4; j++) {
        const int r = r0 + ty + 16 * j;
        const float bj = bias[r];
#pragma unroll
        for (int i = 0; i < 4; i++) {
            const int t = t0 + tx + 16 * i;
            g_U[(size_t)t * R_SZ + r] = acc[i][j] + bj;
        }
    }
}

// ---------------------------------------------------------------------------
// Persistent ESN scan. 128 CTAs, 16 rows each. Weights register-resident
// (scalar float4 — no f32x2 pairing pressure). Cross-CTA state exchange via
// self-validating tagged 16B chunks: poll IS the state load.
// ---------------------------------------------------------------------------
__global__ __launch_bounds__(THREADS_SCAN, 1) void scan_kernel(
    const float* __restrict__ Wres,  // [R_SZ][R_SZ]
    float* __restrict__ out)         // [T_LEN][R_SZ]
{
    __shared__ float  s_sm[R_SZ];            // full state, 8 KB
    __shared__ float  r_sm[ROWS_PER_CTA];    // this CTA's 16 new values

    const float4* s_sm4 = (const float4*)s_sm;

    const int tid  = threadIdx.x;
    const int warp = tid >> 5;
    const int lane = tid & 31;
    const int bid  = blockIdx.x;
    const int rowA = bid * ROWS_PER_CTA + 2 * warp;

    // Preload weights: thread (warp w, lane l) owns rows {rowA,rowA+1},
    // columns 4*l + 128*k (+0..3), k = 0..15.  128 scalar f32 regs.
    float4 wA[16], wB[16];
    {
        const float* pA = Wres + (size_t)rowA * R_SZ + 4 * lane;
        const float* pB = pA + R_SZ;
#pragma unroll
        for (int k = 0; k < 16; k++) {
            wA[k] = *(const float4*)(pA + 128 * k);
            wB[k] = *(const float4*)(pB + 128 * k);
        }
    }

    // lane 0 owns rowA's carry, lane 16 owns rowA+1's carry
    const bool is_owner = (lane == 0) || (lane == 16);
    const int  my_row   = rowA + (lane >> 4);
    float xp = 0.0f;                 // previous value of my_row

    // This thread's 3 chunks (NCHUNK == 3 * THREADS_SCAN).
    const int ch0 = tid * 3;

    for (int t = 0; t < T_LEN; t++) {
        // ---- hoisted independent load: input projection for this step ----
        float u = 0.f;
        if (is_owner) u = __ldg(g_U + (size_t)t * R_SZ + my_row);

        // ---- acquire state for step t: poll tagged chunks (t>0) ----
        if (t == 0) {
            for (int i = tid; i < R_SZ; i += THREADS_SCAN) s_sm[i] = 0.0f;
        } else {
            const float4* buf = g_chunks[t & 1];
#pragma unroll
            for (int i = 0; i < 3; i++) {
                const int ch  = ch0 + i;
                const int sub = ch % CHUNKS_PER_CTA;              // 0..5
                const int row = (ch / CHUNKS_PER_CTA) * ROWS_PER_CTA + 3 * sub;
                float4 v;
                do {
                    v = ld_chunk_volatile(buf + ch);
                } while (__float_as_int(v.w) != t);
                s_sm[row] = v.x;
                if (sub < 5) { s_sm[row + 1] = v.y; s_sm[row + 2] = v.z; }
            }
        }
        __syncthreads();

        // ---- register-resident matvec ----
        float a0 = 0.f, a1 = 0.f;
#pragma unroll
        for (int k = 0; k < 16; k++) {
            const float4 s4 = s_sm4[lane + 32 * k];
            a0 += wA[k].x * s4.x; a0 += wA[k].y * s4.y;
            a0 += wA[k].z * s4.z; a0 += wA[k].w * s4.w;
            a1 += wB[k].x * s4.x; a1 += wB[k].y * s4.y;
            a1 += wB[k].z * s4.z; a1 += wB[k].w * s4.w;
        }

        // ---- split-half reduction: lane 0 -> row A, lane 16 -> row B ----
        a0 += __shfl_xor_sync(0xffffffffu, a0, 16);
        a1 += __shfl_xor_sync(0xffffffffu, a1, 16);
        float v = (lane < 16) ? a0 : a1;
#pragma unroll
        for (int off = 8; off > 0; off >>= 1)
            v += __shfl_xor_sync(0xffffffffu, v, off);

        if (is_owner) {
            const float x = 0.1f * xp + 0.9f * erff(v + u) * INV_SQRT_R;
            xp = x;
            r_sm[2 * warp + (lane >> 4)] = x;
        }
        __syncthreads();

        // ---- publish: tagged chunks (warp 7 lanes 0-5, one STG.128 each,
        //      atomic data+tag => no fence), plain output store (warp 6). ----
        if (warp == 7 && lane < CHUNKS_PER_CTA) {
            float4 c;
            const int r3 = 3 * lane;
            c.x = r_sm[r3];
            c.y = (lane < 5) ? r_sm[r3 + 1] : 0.0f;
            c.z = (lane < 5) ? r_sm[r3 + 2] : 0.0f;
            c.w = __int_as_float(t + 1);
            st_chunk_volatile(&g_chunks[(t + 1) & 1][bid * CHUNKS_PER_CTA + lane], c);
        }
        if (warp == 6 && lane < 4) {
            float4* dst = (float4*)(out + (size_t)t * R_SZ + bid * ROWS_PER_CTA);
            dst[lane] = ((const float4*)r_sm)[lane];
        }
    }
}

// ---------------------------------------------------------------------------
extern "C" void kernel_launch(void* const* d_in, const int* in_sizes, int n_in,
                              void* d_out, int out_size)
{
    const float* input = (const float*)d_in[0];  // [4096][128]
    const float* Win   = (const float*)d_in[1];  // [2048][128]
    const float* Wres  = (const float*)d_in[2];  // [2048][2048]
    const float* bias  = (const float*)d_in[3];  // [2048]
    float* out = (float*)d_out;                  // [4096][2048]

    init_kernel<<<2 * NCHUNK / 256, 256>>>();

    dim3 pg(R_SZ / 64, T_LEN / 64);              // (32, 64)
    proj_kernel<<<pg, 256>>>(input, Win, bias);

    scan_kernel<<<NCTA, THREADS_SCAN>>>(Wres, out);
}